// round 2
// baseline (speedup 1.0000x reference)
#include <cuda_runtime.h>
#include <math.h>

#define DIM   1024
#define BATCH 4
#define SEQ   2048
#define MTOT  (BATCH * SEQ)

// Scratch (allocation-free rule: __device__ globals)
__device__ float g_q[MTOT * DIM];      // 32 MB
__device__ float g_k[MTOT * DIM];      // 32 MB
__device__ float g_v[MTOT * DIM];      // 32 MB
__device__ float g_s[BATCH * SEQ * SEQ]; // 64 MB

// ---------------------------------------------------------------------------
// Tiled SGEMM: C = scale * (A @ op(B)) + bias
//   TRANSB=true : op(B) = B^T, B is [N,K] row-major (K-major, like A)
//   TRANSB=false: op(B) = B,   B is [K,N] row-major
// Tile 128x128x16, 256 threads, 8x8 per-thread micro-tile split as 2x2 float4
// chunks (conflict-free LDS.128 reads, fully coalesced float4 epilogue).
// Requires M%128==0, N%128==0, K%16==0 (all shapes here satisfy this).
// ---------------------------------------------------------------------------
template <bool TRANSB>
__global__ __launch_bounds__(256) void gemm_kernel(
    const float* __restrict__ A, const float* __restrict__ B,
    const float* __restrict__ bias, float* __restrict__ C,
    int M, int N, int K, float scale,
    long strideA, long strideB, long strideC)
{
    constexpr int BM = 128, BN = 128, BK = 16;
    A += (long)blockIdx.z * strideA;
    B += (long)blockIdx.z * strideB;
    C += (long)blockIdx.z * strideC;

    __shared__ __align__(16) float As[BK][BM];
    __shared__ __align__(16) float Bs[BK][BN];

    const int tid = threadIdx.x;
    const int tx  = tid & 15;   // 0..15 -> N direction
    const int ty  = tid >> 4;   // 0..15 -> M direction
    const int m0  = blockIdx.y * BM;
    const int n0  = blockIdx.x * BN;

    float acc[8][8];
#pragma unroll
    for (int i = 0; i < 8; i++)
#pragma unroll
        for (int j = 0; j < 8; j++) acc[i][j] = 0.f;

    for (int k0 = 0; k0 < K; k0 += BK) {
        // --- load A tile: 128 rows x 16 k, store transposed As[k][m] ---
#pragma unroll
        for (int i = 0; i < 2; i++) {
            int v   = tid + i * 256;        // 0..511 float4s
            int row = v >> 2;               // 0..127
            int kv  = (v & 3) << 2;         // 0,4,8,12
            float4 a4 = *reinterpret_cast<const float4*>(
                &A[(long)(m0 + row) * K + k0 + kv]);
            As[kv + 0][row] = a4.x;
            As[kv + 1][row] = a4.y;
            As[kv + 2][row] = a4.z;
            As[kv + 3][row] = a4.w;
        }
        // --- load B tile ---
        if (TRANSB) {
            // B is [N,K] row-major: rows n0..n0+127, cols k0..k0+15
#pragma unroll
            for (int i = 0; i < 2; i++) {
                int v   = tid + i * 256;
                int row = v >> 2;
                int kv  = (v & 3) << 2;
                float4 b4 = *reinterpret_cast<const float4*>(
                    &B[(long)(n0 + row) * K + k0 + kv]);
                Bs[kv + 0][row] = b4.x;
                Bs[kv + 1][row] = b4.y;
                Bs[kv + 2][row] = b4.z;
                Bs[kv + 3][row] = b4.w;
            }
        } else {
            // B is [K,N] row-major: rows k0..k0+15, cols n0..n0+127
#pragma unroll
            for (int i = 0; i < 2; i++) {
                int v   = tid + i * 256;
                int row = v >> 5;           // 0..15
                int c4  = (v & 31) << 2;    // 0..124
                *reinterpret_cast<float4*>(&Bs[row][c4]) =
                    *reinterpret_cast<const float4*>(
                        &B[(long)(k0 + row) * N + n0 + c4]);
            }
        }
        __syncthreads();

        // --- compute ---
#pragma unroll
        for (int kk = 0; kk < BK; kk++) {
            float ra[8], rb[8];
            *reinterpret_cast<float4*>(&ra[0]) =
                *reinterpret_cast<const float4*>(&As[kk][ty * 4]);
            *reinterpret_cast<float4*>(&ra[4]) =
                *reinterpret_cast<const float4*>(&As[kk][64 + ty * 4]);
            *reinterpret_cast<float4*>(&rb[0]) =
                *reinterpret_cast<const float4*>(&Bs[kk][tx * 4]);
            *reinterpret_cast<float4*>(&rb[4]) =
                *reinterpret_cast<const float4*>(&Bs[kk][64 + tx * 4]);
#pragma unroll
            for (int i = 0; i < 8; i++)
#pragma unroll
                for (int j = 0; j < 8; j++)
                    acc[i][j] = fmaf(ra[i], rb[j], acc[i][j]);
        }
        __syncthreads();
    }

    // --- epilogue: scale + bias, float4 stores ---
#pragma unroll
    for (int jj = 0; jj < 2; jj++) {
        int n = n0 + jj * 64 + tx * 4;
        float4 bvec = make_float4(0.f, 0.f, 0.f, 0.f);
        if (bias) bvec = *reinterpret_cast<const float4*>(&bias[n]);
#pragma unroll
        for (int ii = 0; ii < 2; ii++) {
#pragma unroll
            for (int r = 0; r < 4; r++) {
                int m = m0 + ii * 64 + ty * 4 + r;
                float4 o;
                o.x = fmaf(scale, acc[ii * 4 + r][jj * 4 + 0], bvec.x);
                o.y = fmaf(scale, acc[ii * 4 + r][jj * 4 + 1], bvec.y);
                o.z = fmaf(scale, acc[ii * 4 + r][jj * 4 + 2], bvec.z);
                o.w = fmaf(scale, acc[ii * 4 + r][jj * 4 + 3], bvec.w);
                *reinterpret_cast<float4*>(&C[(long)m * N + n]) = o;
            }
        }
    }
}

// ---------------------------------------------------------------------------
// Row softmax over SEQ=2048 elements, one block (256 threads) per row.
// ---------------------------------------------------------------------------
__global__ __launch_bounds__(256) void softmax_kernel(float* __restrict__ S)
{
    float* p = S + (long)blockIdx.x * SEQ;
    const int tid = threadIdx.x;

    float4 v0 = reinterpret_cast<float4*>(p)[tid * 2 + 0];
    float4 v1 = reinterpret_cast<float4*>(p)[tid * 2 + 1];

    __shared__ float red[256];

    float m = fmaxf(fmaxf(fmaxf(v0.x, v0.y), fmaxf(v0.z, v0.w)),
                    fmaxf(fmaxf(v1.x, v1.y), fmaxf(v1.z, v1.w)));
    red[tid] = m;
    __syncthreads();
#pragma unroll
    for (int s = 128; s > 0; s >>= 1) {
        if (tid < s) red[tid] = fmaxf(red[tid], red[tid + s]);
        __syncthreads();
    }
    const float rmax = red[0];
    __syncthreads();

    v0.x = expf(v0.x - rmax); v0.y = expf(v0.y - rmax);
    v0.z = expf(v0.z - rmax); v0.w = expf(v0.w - rmax);
    v1.x = expf(v1.x - rmax); v1.y = expf(v1.y - rmax);
    v1.z = expf(v1.z - rmax); v1.w = expf(v1.w - rmax);

    float sum = (v0.x + v0.y + v0.z + v0.w) + (v1.x + v1.y + v1.z + v1.w);
    red[tid] = sum;
    __syncthreads();
#pragma unroll
    for (int s = 128; s > 0; s >>= 1) {
        if (tid < s) red[tid] += red[tid + s];
        __syncthreads();
    }
    const float inv = 1.f / red[0];

    v0.x *= inv; v0.y *= inv; v0.z *= inv; v0.w *= inv;
    v1.x *= inv; v1.y *= inv; v1.z *= inv; v1.w *= inv;

    reinterpret_cast<float4*>(p)[tid * 2 + 0] = v0;
    reinterpret_cast<float4*>(p)[tid * 2 + 1] = v1;
}

// ---------------------------------------------------------------------------
extern "C" void kernel_launch(void* const* d_in, const int* in_sizes, int n_in,
                              void* d_out, int out_size)
{
    const float* x  = (const float*)d_in[0];
    const float* Wq = (const float*)d_in[1];
    const float* bq = (const float*)d_in[2];
    const float* Wk = (const float*)d_in[3];
    const float* bk = (const float*)d_in[4];
    const float* Wv = (const float*)d_in[5];
    const float* bv = (const float*)d_in[6];
    float* out = (float*)d_out;

    float *q, *k, *v, *s;
    cudaGetSymbolAddress((void**)&q, g_q);
    cudaGetSymbolAddress((void**)&k, g_k);
    cudaGetSymbolAddress((void**)&v, g_v);
    cudaGetSymbolAddress((void**)&s, g_s);

    // QKV projections: [8192,1024] = x[8192,1024] @ W^T[1024,1024] + b
    dim3 gQKV(DIM / 128, MTOT / 128, 1);
    gemm_kernel<true><<<gQKV, 256>>>(x, Wq, bq, q, MTOT, DIM, DIM, 1.f, 0, 0, 0);
    gemm_kernel<true><<<gQKV, 256>>>(x, Wk, bk, k, MTOT, DIM, DIM, 1.f, 0, 0, 0);
    gemm_kernel<true><<<gQKV, 256>>>(x, Wv, bv, v, MTOT, DIM, DIM, 1.f, 0, 0, 0);

    // S = (q @ k^T) * D^-0.5, batched over z
    dim3 gS(SEQ / 128, SEQ / 128, BATCH);
    gemm_kernel<true><<<gS, 256>>>(q, k, nullptr, s, SEQ, SEQ, DIM, 0.03125f,
                                   (long)SEQ * DIM, (long)SEQ * DIM,
                                   (long)SEQ * SEQ);

    // softmax rows
    softmax_kernel<<<BATCH * SEQ, 256>>>(s);

    // out = P @ v, batched over z
    dim3 gO(DIM / 128, SEQ / 128, BATCH);
    gemm_kernel<false><<<gO, 256>>>(s, v, nullptr, out, SEQ, DIM, SEQ, 1.f,
                                    (long)SEQ * SEQ, (long)SEQ * DIM,
                                    (long)SEQ * DIM);
}

// round 5
// speedup vs baseline: 2.9624x; 2.9624x over previous
#include <cuda_runtime.h>
#include <cuda_fp16.h>
#include <cstdint>
#include <math.h>

#define DIM   1024
#define BATCH 4
#define SEQ   2048
#define MTOT  (BATCH * SEQ)
#define KCAT  (3 * DIM)                    // split-K for QKV

#define BK          32                     // K elems per chunk
#define NS          3                      // pipeline stages
#define PITCH_H     40                     // fp16 per smem row (32 + pad)
#define PITCH_B     (PITCH_H * 2)          // 80 bytes
#define PITCH_U     (PITCH_H / 2)          // 20 uint32
#define TILE_B      (128 * PITCH_B)        // 10240 B per operand tile
#define STAGE_B     (2 * TILE_B)           // 20480
#define SMEM_DYN    (NS * STAGE_B)         // 61440

// -------- scratch (__device__ globals per allocation-free rule) --------
__device__ __half g_xcat[(long)MTOT * KCAT];     // 48 MB  [xh | xl | xh]
__device__ __half g_wcat[3][(long)DIM * KCAT];   // 18 MB  [Wh | Wh | Wl] per proj
__device__ __half g_q [(long)MTOT * DIM];        // 16 MB
__device__ __half g_k [(long)MTOT * DIM];        // 16 MB
__device__ __half g_vT[(long)DIM * MTOT];        // 16 MB  vT[d][b*SEQ+m]
__device__ float  g_s [(long)BATCH * SEQ * SEQ]; // 64 MB  logits
__device__ __half g_p [(long)MTOT * SEQ];        // 32 MB  probabilities

// ---------------------------------------------------------------------------
__device__ __forceinline__ void cp16(void* s, const void* g) {
    uint32_t sa = (uint32_t)__cvta_generic_to_shared(s);
    asm volatile("cp.async.cg.shared.global [%0], [%1], 16;"
                 :: "r"(sa), "l"(g) : "memory");
}
__device__ __forceinline__ void cp_commit() {
    asm volatile("cp.async.commit_group;" ::: "memory");
}
template <int N>
__device__ __forceinline__ void cp_wait() {
    asm volatile("cp.async.wait_group %0;" :: "n"(N) : "memory");
}
__device__ __forceinline__ void mma16816(float* c, const uint32_t* a, const uint32_t* b) {
    asm volatile(
        "mma.sync.aligned.m16n8k16.row.col.f32.f16.f16.f32 "
        "{%0,%1,%2,%3}, {%4,%5,%6,%7}, {%8,%9}, {%0,%1,%2,%3};"
        : "+f"(c[0]), "+f"(c[1]), "+f"(c[2]), "+f"(c[3])
        : "r"(a[0]), "r"(a[1]), "r"(a[2]), "r"(a[3]), "r"(b[0]), "r"(b[1]));
}

// ---------------------------------------------------------------------------
// fp16 NT GEMM: C = scale * (A @ B^T) (+ bias).  A:[*,lda], B:[*,ldb] fp16.
// MODE 0: C half [m][n] + bias       MODE 1: C half transposed [n][m] + bias
// MODE 2: C float [m][n] * scale
// ---------------------------------------------------------------------------
template <int MODE>
__global__ __launch_bounds__(256, 2) void gemm_h(
    const __half* __restrict__ A, const __half* __restrict__ B,
    const float* __restrict__ bias, void* __restrict__ Cv,
    int lda, int ldb, int ldc, int K, float scale,
    int aZrow, int bZrow, int bZcol, long cZ)
{
    extern __shared__ __align__(16) char dsmem[];

    const int tid  = threadIdx.x;
    const int wid  = tid >> 5;
    const int lane = tid & 31;
    const int wm   = wid & 1;          // 2 M-slabs of 64
    const int wn   = wid >> 1;         // 4 N-slabs of 32
    const int r    = lane >> 2;
    const int cpr  = lane & 3;

    const int z  = blockIdx.z;
    const int m0 = blockIdx.y * 128;
    const int n0 = blockIdx.x * 128;

    const __half* Ag = A + (long)(z * aZrow + m0) * lda;
    const __half* Bg = B + (long)(z * bZrow + n0) * ldb + (long)z * bZcol;

    const int ldr = tid >> 2;          // 0..63: loader row group
    const int lds = tid & 3;           // 16B segment

    float acc[4][4][4];
#pragma unroll
    for (int i = 0; i < 4; i++)
#pragma unroll
        for (int j = 0; j < 4; j++)
#pragma unroll
            for (int t = 0; t < 4; t++) acc[i][j][t] = 0.f;

    const int nch = K / BK;

    auto load_stage = [&](int slot, int kpos) {
        char* sa = dsmem + slot * STAGE_B;
        char* sb = sa + TILE_B;
#pragma unroll
        for (int h = 0; h < 2; h++) {
            int row = ldr + h * 64;
            cp16(sa + row * PITCH_B + lds * 16, Ag + (long)row * lda + kpos + lds * 8);
            cp16(sb + row * PITCH_B + lds * 16, Bg + (long)row * ldb + kpos + lds * 8);
        }
    };

#pragma unroll
    for (int s = 0; s < NS - 1; s++) { load_stage(s, s * BK); cp_commit(); }

    for (int i = 0; i < nch; i++) {
        cp_wait<NS - 2>();
        __syncthreads();

        int nf = i + NS - 1;
        if (nf < nch) load_stage(nf % NS, nf * BK);
        cp_commit();

        const int slot = i % NS;
        const uint32_t* A32 = reinterpret_cast<const uint32_t*>(dsmem + slot * STAGE_B);
        const uint32_t* B32 = reinterpret_cast<const uint32_t*>(dsmem + slot * STAGE_B + TILE_B);

#pragma unroll
        for (int ks = 0; ks < 2; ks++) {
            uint32_t af[4][4], bf[4][2];
            const int ko = ks * 8;
#pragma unroll
            for (int mt = 0; mt < 4; mt++) {
                int rb = wm * 64 + mt * 16 + r;
                af[mt][0] = A32[rb * PITCH_U + ko + cpr];
                af[mt][1] = A32[(rb + 8) * PITCH_U + ko + cpr];
                af[mt][2] = A32[rb * PITCH_U + ko + 4 + cpr];
                af[mt][3] = A32[(rb + 8) * PITCH_U + ko + 4 + cpr];
            }
#pragma unroll
            for (int nt = 0; nt < 4; nt++) {
                int nb = wn * 32 + nt * 8 + r;
                bf[nt][0] = B32[nb * PITCH_U + ko + cpr];
                bf[nt][1] = B32[nb * PITCH_U + ko + 4 + cpr];
            }
#pragma unroll
            for (int mt = 0; mt < 4; mt++)
#pragma unroll
                for (int nt = 0; nt < 4; nt++)
                    mma16816(acc[mt][nt], af[mt], bf[nt]);
        }
        __syncthreads();
    }
    cp_wait<0>();

    // ---- epilogue ----
#pragma unroll
    for (int mt = 0; mt < 4; mt++) {
#pragma unroll
        for (int nt = 0; nt < 4; nt++) {
            int grow0 = m0 + wm * 64 + mt * 16 + r;
            int gcol  = n0 + wn * 32 + nt * 8 + cpr * 2;
            float* c = acc[mt][nt];
            if (MODE == 0) {
                __half* C = (__half*)Cv;
                float b0 = bias[gcol], b1 = bias[gcol + 1];
                *reinterpret_cast<__half2*>(&C[(long)grow0 * ldc + gcol]) =
                    __floats2half2_rn(c[0] + b0, c[1] + b1);
                *reinterpret_cast<__half2*>(&C[(long)(grow0 + 8) * ldc + gcol]) =
                    __floats2half2_rn(c[2] + b0, c[3] + b1);
            } else if (MODE == 1) {
                __half* C = (__half*)Cv;   // transposed: C[col][row]
                float b0 = bias[gcol], b1 = bias[gcol + 1];
                C[(long)gcol * ldc + grow0]           = __float2half_rn(c[0] + b0);
                C[(long)(gcol + 1) * ldc + grow0]     = __float2half_rn(c[1] + b1);
                C[(long)gcol * ldc + grow0 + 8]       = __float2half_rn(c[2] + b0);
                C[(long)(gcol + 1) * ldc + grow0 + 8] = __float2half_rn(c[3] + b1);
            } else {
                float* C = (float*)Cv + z * cZ;
                *reinterpret_cast<float2*>(&C[(long)grow0 * ldc + gcol]) =
                    make_float2(c[0] * scale, c[1] * scale);
                *reinterpret_cast<float2*>(&C[(long)(grow0 + 8) * ldc + gcol]) =
                    make_float2(c[2] * scale, c[3] * scale);
            }
        }
    }
}

// ---------------------------------------------------------------------------
// Split fp32 -> 3 fp16 blocks along K.
// LO_AT=1: [hi | lo | hi]  (for x)      LO_AT=2: [hi | hi | lo]  (for W)
// Pairing gives xh*Wh + xl*Wh + xh*Wl ~= x*W (missing only xl*Wl ~ 1e-7).
// ---------------------------------------------------------------------------
template <int LO_AT>
__global__ __launch_bounds__(256) void split_kernel(
    const float* __restrict__ in, __half* __restrict__ out, int rows)
{
    long i = (long)blockIdx.x * 256 + threadIdx.x;
    if (i >= (long)rows * DIM) return;
    int row = (int)(i >> 10), c = (int)(i & (DIM - 1));
    float f = in[i];
    __half h = __float2half_rn(f);
    __half l = __float2half_rn(f - __half2float(h));
    long base = (long)row * KCAT;
    out[base + c]           = h;
    out[base + DIM + c]     = (LO_AT == 1) ? l : h;
    out[base + 2 * DIM + c] = (LO_AT == 1) ? h : l;
}

// ---------------------------------------------------------------------------
// Row softmax over SEQ fp32 logits -> fp16 probabilities
// ---------------------------------------------------------------------------
__global__ __launch_bounds__(256) void softmax_kernel(
    const float* __restrict__ S, __half* __restrict__ P)
{
    const float* p = S + (long)blockIdx.x * SEQ;
    __half* o = P + (long)blockIdx.x * SEQ;
    const int tid = threadIdx.x;

    float4 v0 = reinterpret_cast<const float4*>(p)[tid * 2 + 0];
    float4 v1 = reinterpret_cast<const float4*>(p)[tid * 2 + 1];

    __shared__ float red[256];

    float mx = fmaxf(fmaxf(fmaxf(v0.x, v0.y), fmaxf(v0.z, v0.w)),
                     fmaxf(fmaxf(v1.x, v1.y), fmaxf(v1.z, v1.w)));
    red[tid] = mx;
    __syncthreads();
#pragma unroll
    for (int s = 128; s > 0; s >>= 1) {
        if (tid < s) red[tid] = fmaxf(red[tid], red[tid + s]);
        __syncthreads();
    }
    const float rmax = red[0];
    __syncthreads();

    v0.x = expf(v0.x - rmax); v0.y = expf(v0.y - rmax);
    v0.z = expf(v0.z - rmax); v0.w = expf(v0.w - rmax);
    v1.x = expf(v1.x - rmax); v1.y = expf(v1.y - rmax);
    v1.z = expf(v1.z - rmax); v1.w = expf(v1.w - rmax);

    red[tid] = (v0.x + v0.y + v0.z + v0.w) + (v1.x + v1.y + v1.z + v1.w);
    __syncthreads();
#pragma unroll
    for (int s = 128; s > 0; s >>= 1) {
        if (tid < s) red[tid] += red[tid + s];
        __syncthreads();
    }
    const float inv = 1.f / red[0];

    __half2 h[4];
    h[0] = __floats2half2_rn(v0.x * inv, v0.y * inv);
    h[1] = __floats2half2_rn(v0.z * inv, v0.w * inv);
    h[2] = __floats2half2_rn(v1.x * inv, v1.y * inv);
    h[3] = __floats2half2_rn(v1.z * inv, v1.w * inv);
    *reinterpret_cast<uint4*>(&o[tid * 8]) = *reinterpret_cast<uint4*>(h);
}

// ---------------------------------------------------------------------------
extern "C" void kernel_launch(void* const* d_in, const int* in_sizes, int n_in,
                              void* d_out, int out_size)
{
    const float* x  = (const float*)d_in[0];
    const float* Wq = (const float*)d_in[1];
    const float* bq = (const float*)d_in[2];
    const float* Wk = (const float*)d_in[3];
    const float* bk = (const float*)d_in[4];
    const float* Wv = (const float*)d_in[5];
    const float* bv = (const float*)d_in[6];
    float* out = (float*)d_out;

    __half *xc, *wc, *q, *k, *vT, *p;
    float* s;
    cudaGetSymbolAddress((void**)&xc, g_xcat);
    cudaGetSymbolAddress((void**)&wc, g_wcat);
    cudaGetSymbolAddress((void**)&q,  g_q);
    cudaGetSymbolAddress((void**)&k,  g_k);
    cudaGetSymbolAddress((void**)&vT, g_vT);
    cudaGetSymbolAddress((void**)&s,  g_s);
    cudaGetSymbolAddress((void**)&p,  g_p);
    __half* wcq = wc;
    __half* wck = wc + (long)DIM * KCAT;
    __half* wcv = wc + 2 * (long)DIM * KCAT;

    cudaFuncSetAttribute(gemm_h<0>, cudaFuncAttributeMaxDynamicSharedMemorySize, SMEM_DYN);
    cudaFuncSetAttribute(gemm_h<1>, cudaFuncAttributeMaxDynamicSharedMemorySize, SMEM_DYN);
    cudaFuncSetAttribute(gemm_h<2>, cudaFuncAttributeMaxDynamicSharedMemorySize, SMEM_DYN);

    // 0) split inputs: x -> [hi|lo|hi], W -> [hi|hi|lo]
    split_kernel<1><<<(MTOT * DIM + 255) / 256, 256>>>(x,  xc,  MTOT);
    split_kernel<2><<<(DIM * DIM + 255) / 256, 256>>>(Wq, wcq, DIM);
    split_kernel<2><<<(DIM * DIM + 255) / 256, 256>>>(Wk, wck, DIM);
    split_kernel<2><<<(DIM * DIM + 255) / 256, 256>>>(Wv, wcv, DIM);

    // 1) QKV projections (split-K=3072): q,k normal half; v transposed half
    dim3 gQKV(DIM / 128, MTOT / 128, 1);
    gemm_h<0><<<gQKV, 256, SMEM_DYN>>>(xc, wcq, bq, q,  KCAT, KCAT, DIM,  KCAT, 1.f, 0, 0, 0, 0);
    gemm_h<0><<<gQKV, 256, SMEM_DYN>>>(xc, wck, bk, k,  KCAT, KCAT, DIM,  KCAT, 1.f, 0, 0, 0, 0);
    gemm_h<1><<<gQKV, 256, SMEM_DYN>>>(xc, wcv, bv, vT, KCAT, KCAT, MTOT, KCAT, 1.f, 0, 0, 0, 0);

    // 2) S = (q @ k^T) * DIM^-0.5, batched over z
    dim3 gS(SEQ / 128, SEQ / 128, BATCH);
    gemm_h<2><<<gS, 256, SMEM_DYN>>>(q, k, nullptr, s, DIM, DIM, SEQ, DIM, 0.03125f,
                                     SEQ, SEQ, 0, (long)SEQ * SEQ);

    // 3) softmax rows -> fp16 P
    softmax_kernel<<<MTOT, 256>>>(s, p);

    // 4) out = P @ vT^T, batched over z
    dim3 gO(DIM / 128, SEQ / 128, BATCH);
    gemm_h<2><<<gO, 256, SMEM_DYN>>>(p, vT, nullptr, out, SEQ, MTOT, DIM, SEQ, 1.f,
                                     SEQ, 0, SEQ, (long)SEQ * DIM);
}

// round 6
// speedup vs baseline: 4.2563x; 1.4368x over previous
#include <cuda_runtime.h>
#include <cuda_fp16.h>
#include <cstdint>
#include <math.h>

#define DIM   1024
#define BATCH 4
#define SEQ   2048
#define MTOT  (BATCH * SEQ)
#define K2    (2 * DIM)                    // 2-term split-K for QKV
#define NQKV  (3 * DIM)                    // fused QKV output width

#define BK          32                     // K elems per chunk
#define NS          4                      // pipeline stages
#define PITCH_H     40                     // fp16 per smem row (32 + pad)
#define PITCH_B     (PITCH_H * 2)          // 80 bytes
#define TILE_B      (128 * PITCH_B)        // 10240 B per operand tile
#define STAGE_B     (2 * TILE_B)           // 20480
#define SMEM_DYN    (NS * STAGE_B)         // 81920

// -------- scratch (__device__ globals per allocation-free rule) --------
__device__ __half g_xc  [(long)MTOT * K2];       // 32 MB  [xh | xl]
__device__ __half g_wc  [(long)NQKV * K2];       // 12 MB  [Wh | Wh] rows (q,k,v stacked)
__device__ float  g_bc  [NQKV];                  // concat bias
__device__ __half g_qkv [(long)MTOT * NQKV];     // 48 MB  [q | k | v] per row
__device__ __half g_vT  [(long)DIM * MTOT];      // 16 MB  vT[d][b*SEQ+m]
__device__ float  g_s   [(long)BATCH * SEQ * SEQ]; // 64 MB logits
__device__ __half g_p   [(long)MTOT * SEQ];      // 32 MB  probabilities

// ---------------------------------------------------------------------------
__device__ __forceinline__ void cp16(void* s, const void* g) {
    uint32_t sa = (uint32_t)__cvta_generic_to_shared(s);
    asm volatile("cp.async.cg.shared.global [%0], [%1], 16;"
                 :: "r"(sa), "l"(g) : "memory");
}
__device__ __forceinline__ void cp_commit() {
    asm volatile("cp.async.commit_group;" ::: "memory");
}
template <int N>
__device__ __forceinline__ void cp_wait() {
    asm volatile("cp.async.wait_group %0;" :: "n"(N) : "memory");
}
__device__ __forceinline__ void ldmx4(uint32_t* r, uint32_t addr) {
    asm volatile("ldmatrix.sync.aligned.m8n8.x4.shared.b16 {%0,%1,%2,%3}, [%4];"
                 : "=r"(r[0]), "=r"(r[1]), "=r"(r[2]), "=r"(r[3]) : "r"(addr));
}
__device__ __forceinline__ void mma16816(float* c, const uint32_t* a, const uint32_t* b) {
    asm volatile(
        "mma.sync.aligned.m16n8k16.row.col.f32.f16.f16.f32 "
        "{%0,%1,%2,%3}, {%4,%5,%6,%7}, {%8,%9}, {%0,%1,%2,%3};"
        : "+f"(c[0]), "+f"(c[1]), "+f"(c[2]), "+f"(c[3])
        : "r"(a[0]), "r"(a[1]), "r"(a[2]), "r"(a[3]), "r"(b[0]), "r"(b[1]));
}

// ---------------------------------------------------------------------------
// fp16 NT GEMM: C = scale * (A @ B^T) (+ bias)
// MODE 0: C half [m][n] + bias       MODE 2: C float [m][n] * scale
// ---------------------------------------------------------------------------
template <int MODE>
__global__ __launch_bounds__(256, 2) void gemm_h(
    const __half* __restrict__ A, const __half* __restrict__ B,
    const float* __restrict__ bias, void* __restrict__ Cv,
    int lda, int ldb, int ldc, int K, float scale,
    int aZrow, int bZrow, int bZcol, long cZ)
{
    extern __shared__ __align__(16) char dsmem[];

    const int tid  = threadIdx.x;
    const int wid  = tid >> 5;
    const int lane = tid & 31;
    const int wm   = wid & 1;          // 2 M-slabs of 64
    const int wn   = wid >> 1;         // 4 N-slabs of 32
    const int r    = lane >> 2;
    const int cpr  = lane & 3;
    const int lj   = lane >> 3;        // ldmatrix address group
    const int lr   = lane & 7;

    const int z  = blockIdx.z;
    const int m0 = blockIdx.y * 128;
    const int n0 = blockIdx.x * 128;

    const __half* Ag = A + (long)(z * aZrow + m0) * lda;
    const __half* Bg = B + (long)(z * bZrow + n0) * ldb + (long)z * bZcol;

    const int ldr = tid >> 2;          // loader row 0..63 (x2)
    const int lds = tid & 3;           // 16B segment

    const uint32_t smem0 = (uint32_t)__cvta_generic_to_shared(dsmem);

    // ldmatrix per-thread byte offsets within a tile
    uint32_t aoff[4], boff[2];
#pragma unroll
    for (int mt = 0; mt < 4; mt++)
        aoff[mt] = (uint32_t)((wm * 64 + mt * 16 + (lj & 1) * 8 + lr) * PITCH_B
                              + (lj >> 1) * 16);
#pragma unroll
    for (int pq = 0; pq < 2; pq++)
        boff[pq] = (uint32_t)((wn * 32 + (pq * 2 + (lj >> 1)) * 8 + lr) * PITCH_B
                              + (lj & 1) * 16);

    float acc[4][4][4];
#pragma unroll
    for (int i = 0; i < 4; i++)
#pragma unroll
        for (int j = 0; j < 4; j++)
#pragma unroll
            for (int t = 0; t < 4; t++) acc[i][j][t] = 0.f;

    const int nch = K / BK;

    auto load_stage = [&](int slot, int kpos) {
        char* sa = dsmem + slot * STAGE_B;
        char* sb = sa + TILE_B;
#pragma unroll
        for (int h = 0; h < 2; h++) {
            int row = ldr + h * 64;
            cp16(sa + row * PITCH_B + lds * 16, Ag + (long)row * lda + kpos + lds * 8);
            cp16(sb + row * PITCH_B + lds * 16, Bg + (long)row * ldb + kpos + lds * 8);
        }
    };

#pragma unroll
    for (int s = 0; s < NS - 1; s++) { load_stage(s, s * BK); cp_commit(); }

    for (int i = 0; i < nch; i++) {
        cp_wait<NS - 2>();
        __syncthreads();

        int nf = i + NS - 1;
        if (nf < nch) load_stage(nf % NS, nf * BK);
        cp_commit();

        const int slot = i % NS;
        const uint32_t sa32 = smem0 + slot * STAGE_B;
        const uint32_t sb32 = sa32 + TILE_B;

#pragma unroll
        for (int ks = 0; ks < 2; ks++) {
            uint32_t af[4][4], bf[2][4];
#pragma unroll
            for (int mt = 0; mt < 4; mt++)
                ldmx4(af[mt], sa32 + aoff[mt] + ks * 32);
#pragma unroll
            for (int pq = 0; pq < 2; pq++)
                ldmx4(bf[pq], sb32 + boff[pq] + ks * 32);
#pragma unroll
            for (int mt = 0; mt < 4; mt++)
#pragma unroll
                for (int nt = 0; nt < 4; nt++)
                    mma16816(acc[mt][nt], af[mt], &bf[nt >> 1][(nt & 1) * 2]);
        }
        __syncthreads();
    }
    cp_wait<0>();

    // ---- epilogue ----
#pragma unroll
    for (int mt = 0; mt < 4; mt++) {
#pragma unroll
        for (int nt = 0; nt < 4; nt++) {
            int grow0 = m0 + wm * 64 + mt * 16 + r;
            int gcol  = n0 + wn * 32 + nt * 8 + cpr * 2;
            float* c = acc[mt][nt];
            if (MODE == 0) {
                __half* C = (__half*)Cv;
                float b0 = bias[gcol], b1 = bias[gcol + 1];
                *reinterpret_cast<__half2*>(&C[(long)grow0 * ldc + gcol]) =
                    __floats2half2_rn(c[0] + b0, c[1] + b1);
                *reinterpret_cast<__half2*>(&C[(long)(grow0 + 8) * ldc + gcol]) =
                    __floats2half2_rn(c[2] + b0, c[3] + b1);
            } else {
                float* C = (float*)Cv + z * cZ;
                *reinterpret_cast<float2*>(&C[(long)grow0 * ldc + gcol]) =
                    make_float2(c[0] * scale, c[1] * scale);
                *reinterpret_cast<float2*>(&C[(long)(grow0 + 8) * ldc + gcol]) =
                    make_float2(c[2] * scale, c[3] * scale);
            }
        }
    }
}

// ---------------------------------------------------------------------------
// x -> [hi | lo] fp16 along K
// ---------------------------------------------------------------------------
__global__ __launch_bounds__(256) void split_x(
    const float* __restrict__ in, __half* __restrict__ out)
{
    long i = (long)blockIdx.x * 256 + threadIdx.x;
    if (i >= (long)MTOT * DIM) return;
    int row = (int)(i >> 10), c = (int)(i & (DIM - 1));
    float f = in[i];
    __half h = __float2half_rn(f);
    __half l = __float2half_rn(f - __half2float(h));
    long base = (long)row * K2;
    out[base + c]       = h;
    out[base + DIM + c] = l;
}

// W -> [hi | hi] fp16 rows at stacked offset
__global__ __launch_bounds__(256) void split_w(
    const float* __restrict__ in, __half* __restrict__ out, int rowoff)
{
    long i = (long)blockIdx.x * 256 + threadIdx.x;
    if (i >= (long)DIM * DIM) return;
    int row = (int)(i >> 10), c = (int)(i & (DIM - 1));
    __half h = __float2half_rn(in[i]);
    long base = (long)(rowoff + row) * K2;
    out[base + c]       = h;
    out[base + DIM + c] = h;
}

__global__ void concat_bias(const float* a, const float* b, const float* c,
                            float* o)
{
    int i = blockIdx.x * 256 + threadIdx.x;
    if (i < DIM) { o[i] = a[i]; o[DIM + i] = b[i]; o[2 * DIM + i] = c[i]; }
}

// ---------------------------------------------------------------------------
// Transpose v slice of qkv ([m][2048+d], ld NQKV) -> vT [d][m]
// ---------------------------------------------------------------------------
__global__ __launch_bounds__(256) void transpose_v(
    const __half* __restrict__ src, __half* __restrict__ dst)
{
    __shared__ __half t[32][33];
    int d0 = blockIdx.x * 32, m0 = blockIdx.y * 32;
    int tx = threadIdx.x & 31, ty = threadIdx.x >> 5;   // 32 x 8
#pragma unroll
    for (int i = 0; i < 4; i++)
        t[ty + i * 8][tx] = src[(long)(m0 + ty + i * 8) * NQKV + 2 * DIM + d0 + tx];
    __syncthreads();
#pragma unroll
    for (int i = 0; i < 4; i++)
        dst[(long)(d0 + ty + i * 8) * MTOT + m0 + tx] = t[tx][ty + i * 8];
}

// ---------------------------------------------------------------------------
// Row softmax over SEQ fp32 logits -> fp16 probabilities
// ---------------------------------------------------------------------------
__global__ __launch_bounds__(256) void softmax_kernel(
    const float* __restrict__ S, __half* __restrict__ P)
{
    const float* p = S + (long)blockIdx.x * SEQ;
    __half* o = P + (long)blockIdx.x * SEQ;
    const int tid = threadIdx.x;

    float4 v0 = reinterpret_cast<const float4*>(p)[tid * 2 + 0];
    float4 v1 = reinterpret_cast<const float4*>(p)[tid * 2 + 1];

    __shared__ float red[256];

    float mx = fmaxf(fmaxf(fmaxf(v0.x, v0.y), fmaxf(v0.z, v0.w)),
                     fmaxf(fmaxf(v1.x, v1.y), fmaxf(v1.z, v1.w)));
    red[tid] = mx;
    __syncthreads();
#pragma unroll
    for (int s = 128; s > 0; s >>= 1) {
        if (tid < s) red[tid] = fmaxf(red[tid], red[tid + s]);
        __syncthreads();
    }
    const float rmax = red[0];
    __syncthreads();

    v0.x = expf(v0.x - rmax); v0.y = expf(v0.y - rmax);
    v0.z = expf(v0.z - rmax); v0.w = expf(v0.w - rmax);
    v1.x = expf(v1.x - rmax); v1.y = expf(v1.y - rmax);
    v1.z = expf(v1.z - rmax); v1.w = expf(v1.w - rmax);

    red[tid] = (v0.x + v0.y + v0.z + v0.w) + (v1.x + v1.y + v1.z + v1.w);
    __syncthreads();
#pragma unroll
    for (int s = 128; s > 0; s >>= 1) {
        if (tid < s) red[tid] += red[tid + s];
        __syncthreads();
    }
    const float inv = 1.f / red[0];

    __half2 h[4];
    h[0] = __floats2half2_rn(v0.x * inv, v0.y * inv);
    h[1] = __floats2half2_rn(v0.z * inv, v0.w * inv);
    h[2] = __floats2half2_rn(v1.x * inv, v1.y * inv);
    h[3] = __floats2half2_rn(v1.z * inv, v1.w * inv);
    *reinterpret_cast<uint4*>(&o[tid * 8]) = *reinterpret_cast<uint4*>(h);
}

// ---------------------------------------------------------------------------
extern "C" void kernel_launch(void* const* d_in, const int* in_sizes, int n_in,
                              void* d_out, int out_size)
{
    const float* x  = (const float*)d_in[0];
    const float* Wq = (const float*)d_in[1];
    const float* bq = (const float*)d_in[2];
    const float* Wk = (const float*)d_in[3];
    const float* bk = (const float*)d_in[4];
    const float* Wv = (const float*)d_in[5];
    const float* bv = (const float*)d_in[6];
    float* out = (float*)d_out;

    __half *xc, *wc, *qkv, *vT, *p;
    float *s, *bc;
    cudaGetSymbolAddress((void**)&xc,  g_xc);
    cudaGetSymbolAddress((void**)&wc,  g_wc);
    cudaGetSymbolAddress((void**)&bc,  g_bc);
    cudaGetSymbolAddress((void**)&qkv, g_qkv);
    cudaGetSymbolAddress((void**)&vT,  g_vT);
    cudaGetSymbolAddress((void**)&s,   g_s);
    cudaGetSymbolAddress((void**)&p,   g_p);

    cudaFuncSetAttribute(gemm_h<0>, cudaFuncAttributeMaxDynamicSharedMemorySize, SMEM_DYN);
    cudaFuncSetAttribute(gemm_h<2>, cudaFuncAttributeMaxDynamicSharedMemorySize, SMEM_DYN);

    // 0) splits + bias concat
    split_x<<<(MTOT * DIM + 255) / 256, 256>>>(x, xc);
    split_w<<<(DIM * DIM + 255) / 256, 256>>>(Wq, wc, 0);
    split_w<<<(DIM * DIM + 255) / 256, 256>>>(Wk, wc, DIM);
    split_w<<<(DIM * DIM + 255) / 256, 256>>>(Wv, wc, 2 * DIM);
    concat_bias<<<(DIM + 255) / 256, 256>>>(bq, bk, bv, bc);

    // 1) fused QKV: qkv[8192][3072] = xc @ wc^T + bc  (K=2048)
    dim3 gQKV(NQKV / 128, MTOT / 128, 1);
    gemm_h<0><<<gQKV, 256, SMEM_DYN>>>(xc, wc, bc, qkv,
                                       K2, K2, NQKV, K2, 1.f, 0, 0, 0, 0);

    // 1b) transpose v slice -> vT
    dim3 gT(DIM / 32, MTOT / 32);
    transpose_v<<<gT, 256>>>(qkv, vT);

    // 2) S = (q @ k^T) * DIM^-0.5, batched over z
    dim3 gS(SEQ / 128, SEQ / 128, BATCH);
    gemm_h<2><<<gS, 256, SMEM_DYN>>>(qkv, qkv + DIM, nullptr, s,
                                     NQKV, NQKV, SEQ, DIM, 0.03125f,
                                     SEQ, SEQ, 0, (long)SEQ * SEQ);

    // 3) softmax rows -> fp16 P
    softmax_kernel<<<MTOT, 256>>>(s, p);

    // 4) out = P @ vT^T, batched over z
    dim3 gO(DIM / 128, SEQ / 128, BATCH);
    gemm_h<2><<<gO, 256, SMEM_DYN>>>(p, vT, nullptr, out,
                                     SEQ, MTOT, DIM, SEQ, 1.f,
                                     SEQ, 0, SEQ, (long)SEQ * DIM);
}

// round 7
// speedup vs baseline: 6.2929x; 1.4785x over previous
#include <cuda_runtime.h>
#include <cuda_fp16.h>
#include <cstdint>
#include <math.h>

#define DIM   1024
#define BATCH 4
#define SEQ   2048
#define MTOT  (BATCH * SEQ)
#define NQKV  (3 * DIM)                    // fused QKV output width

#define BK          32                     // K elems per chunk
#define NS          4                      // pipeline stages
#define PITCH_H     40                     // fp16 per smem row (32 + pad)
#define PITCH_B     (PITCH_H * 2)          // 80 bytes
#define TILE_B      (128 * PITCH_B)        // 10240 B per operand tile
#define STAGE_B     (2 * TILE_B)           // 20480
#define SMEM_DYN    (NS * STAGE_B)         // 81920

// -------- scratch (__device__ globals per allocation-free rule) --------
__device__ __half g_xh  [(long)MTOT * DIM];      // 16 MB  fp16 x
__device__ __half g_wh  [(long)NQKV * DIM];      //  6 MB  fp16 W rows (q,k,v stacked)
__device__ float  g_bc  [NQKV];                  // concat bias
__device__ __half g_qkv [(long)MTOT * NQKV];     // 48 MB  [q | k | v] per row
__device__ __half g_vT  [(long)DIM * MTOT];      // 16 MB  vT[d][b*SEQ+m]
__device__ float  g_s   [(long)BATCH * SEQ * SEQ]; // 64 MB logits
__device__ __half g_p   [(long)MTOT * SEQ];      // 32 MB  probabilities

// ---------------------------------------------------------------------------
__device__ __forceinline__ void cp16(void* s, const void* g) {
    uint32_t sa = (uint32_t)__cvta_generic_to_shared(s);
    asm volatile("cp.async.cg.shared.global [%0], [%1], 16;"
                 :: "r"(sa), "l"(g) : "memory");
}
__device__ __forceinline__ void cp_commit() {
    asm volatile("cp.async.commit_group;" ::: "memory");
}
template <int N>
__device__ __forceinline__ void cp_wait() {
    asm volatile("cp.async.wait_group %0;" :: "n"(N) : "memory");
}
__device__ __forceinline__ void ldmx4(uint32_t* r, uint32_t addr) {
    asm volatile("ldmatrix.sync.aligned.m8n8.x4.shared.b16 {%0,%1,%2,%3}, [%4];"
                 : "=r"(r[0]), "=r"(r[1]), "=r"(r[2]), "=r"(r[3]) : "r"(addr));
}
__device__ __forceinline__ void mma16816(float* c, const uint32_t* a, const uint32_t* b) {
    asm volatile(
        "mma.sync.aligned.m16n8k16.row.col.f32.f16.f16.f32 "
        "{%0,%1,%2,%3}, {%4,%5,%6,%7}, {%8,%9}, {%0,%1,%2,%3};"
        : "+f"(c[0]), "+f"(c[1]), "+f"(c[2]), "+f"(c[3])
        : "r"(a[0]), "r"(a[1]), "r"(a[2]), "r"(a[3]), "r"(b[0]), "r"(b[1]));
}

// ---------------------------------------------------------------------------
// fp16 NT GEMM: C = scale * (A @ B^T) (+ bias)
// MODE 0: C half [m][n] + bias       MODE 2: C float [m][n] * scale
// Single __syncthreads per mainloop iteration (issue-after-compute):
// at iter i, loads target slot (i+NS-1)%NS == (i-1)%NS, whose readers all
// completed compute i-1 before this iteration's barrier.
// ---------------------------------------------------------------------------
template <int MODE>
__global__ __launch_bounds__(256, 2) void gemm_h(
    const __half* __restrict__ A, const __half* __restrict__ B,
    const float* __restrict__ bias, void* __restrict__ Cv,
    int lda, int ldb, int ldc, int K, float scale,
    int aZrow, int bZrow, int bZcol, long cZ)
{
    extern __shared__ __align__(16) char dsmem[];

    const int tid  = threadIdx.x;
    const int wid  = tid >> 5;
    const int lane = tid & 31;
    const int wm   = wid & 1;          // 2 M-slabs of 64
    const int wn   = wid >> 1;         // 4 N-slabs of 32
    const int r    = lane >> 2;
    const int cpr  = lane & 3;
    const int lj   = lane >> 3;        // ldmatrix address group
    const int lr   = lane & 7;

    const int z  = blockIdx.z;
    const int m0 = blockIdx.y * 128;
    const int n0 = blockIdx.x * 128;

    const __half* Ag = A + (long)(z * aZrow + m0) * lda;
    const __half* Bg = B + (long)(z * bZrow + n0) * ldb + (long)z * bZcol;

    const int ldr = tid >> 2;          // loader row 0..63 (x2)
    const int lds = tid & 3;           // 16B segment

    const uint32_t smem0 = (uint32_t)__cvta_generic_to_shared(dsmem);

    // ldmatrix per-thread byte offsets within a tile
    uint32_t aoff[4], boff[2];
#pragma unroll
    for (int mt = 0; mt < 4; mt++)
        aoff[mt] = (uint32_t)((wm * 64 + mt * 16 + (lj & 1) * 8 + lr) * PITCH_B
                              + (lj >> 1) * 16);
#pragma unroll
    for (int pq = 0; pq < 2; pq++)
        boff[pq] = (uint32_t)((wn * 32 + (pq * 2 + (lj >> 1)) * 8 + lr) * PITCH_B
                              + (lj & 1) * 16);

    float acc[4][4][4];
#pragma unroll
    for (int i = 0; i < 4; i++)
#pragma unroll
        for (int j = 0; j < 4; j++)
#pragma unroll
            for (int t = 0; t < 4; t++) acc[i][j][t] = 0.f;

    const int nch = K / BK;

    auto load_stage = [&](int slot, int kpos) {
        char* sa = dsmem + slot * STAGE_B;
        char* sb = sa + TILE_B;
#pragma unroll
        for (int h = 0; h < 2; h++) {
            int row = ldr + h * 64;
            cp16(sa + row * PITCH_B + lds * 16, Ag + (long)row * lda + kpos + lds * 8);
            cp16(sb + row * PITCH_B + lds * 16, Bg + (long)row * ldb + kpos + lds * 8);
        }
    };

#pragma unroll
    for (int s = 0; s < NS - 1; s++) { load_stage(s, s * BK); cp_commit(); }

    for (int i = 0; i < nch; i++) {
        cp_wait<NS - 2>();
        __syncthreads();

        const int slot = i % NS;
        const uint32_t sa32 = smem0 + slot * STAGE_B;
        const uint32_t sb32 = sa32 + TILE_B;

#pragma unroll
        for (int ks = 0; ks < 2; ks++) {
            uint32_t af[4][4], bf[2][4];
#pragma unroll
            for (int mt = 0; mt < 4; mt++)
                ldmx4(af[mt], sa32 + aoff[mt] + ks * 32);
#pragma unroll
            for (int pq = 0; pq < 2; pq++)
                ldmx4(bf[pq], sb32 + boff[pq] + ks * 32);
#pragma unroll
            for (int mt = 0; mt < 4; mt++)
#pragma unroll
                for (int nt = 0; nt < 4; nt++)
                    mma16816(acc[mt][nt], af[mt], &bf[nt >> 1][(nt & 1) * 2]);
        }

        int nf = i + NS - 1;
        if (nf < nch) load_stage(nf % NS, nf * BK);
        cp_commit();
    }
    cp_wait<0>();

    // ---- epilogue ----
#pragma unroll
    for (int mt = 0; mt < 4; mt++) {
#pragma unroll
        for (int nt = 0; nt < 4; nt++) {
            int grow0 = m0 + wm * 64 + mt * 16 + r;
            int gcol  = n0 + wn * 32 + nt * 8 + cpr * 2;
            float* c = acc[mt][nt];
            if (MODE == 0) {
                __half* C = (__half*)Cv;
                float b0 = bias[gcol], b1 = bias[gcol + 1];
                *reinterpret_cast<__half2*>(&C[(long)grow0 * ldc + gcol]) =
                    __floats2half2_rn(c[0] + b0, c[1] + b1);
                *reinterpret_cast<__half2*>(&C[(long)(grow0 + 8) * ldc + gcol]) =
                    __floats2half2_rn(c[2] + b0, c[3] + b1);
            } else {
                float* C = (float*)Cv + z * cZ;
                *reinterpret_cast<float2*>(&C[(long)grow0 * ldc + gcol]) =
                    make_float2(c[0] * scale, c[1] * scale);
                *reinterpret_cast<float2*>(&C[(long)(grow0 + 8) * ldc + gcol]) =
                    make_float2(c[2] * scale, c[3] * scale);
            }
        }
    }
}

// ---------------------------------------------------------------------------
// fp32 -> fp16 convert (vectorized)
// ---------------------------------------------------------------------------
__global__ __launch_bounds__(256) void conv_h(
    const float* __restrict__ in, __half* __restrict__ out, long n4)
{
    long i = (long)blockIdx.x * 256 + threadIdx.x;
    if (i >= n4) return;
    float4 v = reinterpret_cast<const float4*>(in)[i];
    __half2 h[2];
    h[0] = __floats2half2_rn(v.x, v.y);
    h[1] = __floats2half2_rn(v.z, v.w);
    *reinterpret_cast<uint2*>(&out[i * 4]) = *reinterpret_cast<uint2*>(h);
}

__global__ void concat_bias(const float* a, const float* b, const float* c,
                            float* o)
{
    int i = blockIdx.x * 256 + threadIdx.x;
    if (i < DIM) { o[i] = a[i]; o[DIM + i] = b[i]; o[2 * DIM + i] = c[i]; }
}

// ---------------------------------------------------------------------------
// Transpose v slice of qkv ([m][2048+d], ld NQKV) -> vT [d][m]
// ---------------------------------------------------------------------------
__global__ __launch_bounds__(256) void transpose_v(
    const __half* __restrict__ src, __half* __restrict__ dst)
{
    __shared__ __half t[32][33];
    int d0 = blockIdx.x * 32, m0 = blockIdx.y * 32;
    int tx = threadIdx.x & 31, ty = threadIdx.x >> 5;   // 32 x 8
#pragma unroll
    for (int i = 0; i < 4; i++)
        t[ty + i * 8][tx] = src[(long)(m0 + ty + i * 8) * NQKV + 2 * DIM + d0 + tx];
    __syncthreads();
#pragma unroll
    for (int i = 0; i < 4; i++)
        dst[(long)(d0 + ty + i * 8) * MTOT + m0 + tx] = t[tx][ty + i * 8];
}

// ---------------------------------------------------------------------------
// Row softmax over SEQ fp32 logits -> fp16 probabilities
// ---------------------------------------------------------------------------
__global__ __launch_bounds__(256) void softmax_kernel(
    const float* __restrict__ S, __half* __restrict__ P)
{
    const float* p = S + (long)blockIdx.x * SEQ;
    __half* o = P + (long)blockIdx.x * SEQ;
    const int tid = threadIdx.x;

    float4 v0 = reinterpret_cast<const float4*>(p)[tid * 2 + 0];
    float4 v1 = reinterpret_cast<const float4*>(p)[tid * 2 + 1];

    __shared__ float red[256];

    float mx = fmaxf(fmaxf(fmaxf(v0.x, v0.y), fmaxf(v0.z, v0.w)),
                     fmaxf(fmaxf(v1.x, v1.y), fmaxf(v1.z, v1.w)));
    red[tid] = mx;
    __syncthreads();
#pragma unroll
    for (int s = 128; s > 0; s >>= 1) {
        if (tid < s) red[tid] = fmaxf(red[tid], red[tid + s]);
        __syncthreads();
    }
    const float rmax = red[0];
    __syncthreads();

    v0.x = expf(v0.x - rmax); v0.y = expf(v0.y - rmax);
    v0.z = expf(v0.z - rmax); v0.w = expf(v0.w - rmax);
    v1.x = expf(v1.x - rmax); v1.y = expf(v1.y - rmax);
    v1.z = expf(v1.z - rmax); v1.w = expf(v1.w - rmax);

    red[tid] = (v0.x + v0.y + v0.z + v0.w) + (v1.x + v1.y + v1.z + v1.w);
    __syncthreads();
#pragma unroll
    for (int s = 128; s > 0; s >>= 1) {
        if (tid < s) red[tid] += red[tid + s];
        __syncthreads();
    }
    const float inv = 1.f / red[0];

    __half2 h[4];
    h[0] = __floats2half2_rn(v0.x * inv, v0.y * inv);
    h[1] = __floats2half2_rn(v0.z * inv, v0.w * inv);
    h[2] = __floats2half2_rn(v1.x * inv, v1.y * inv);
    h[3] = __floats2half2_rn(v1.z * inv, v1.w * inv);
    *reinterpret_cast<uint4*>(&o[tid * 8]) = *reinterpret_cast<uint4*>(h);
}

// ---------------------------------------------------------------------------
extern "C" void kernel_launch(void* const* d_in, const int* in_sizes, int n_in,
                              void* d_out, int out_size)
{
    const float* x  = (const float*)d_in[0];
    const float* Wq = (const float*)d_in[1];
    const float* bq = (const float*)d_in[2];
    const float* Wk = (const float*)d_in[3];
    const float* bk = (const float*)d_in[4];
    const float* Wv = (const float*)d_in[5];
    const float* bv = (const float*)d_in[6];
    float* out = (float*)d_out;

    __half *xh, *wh, *qkv, *vT, *p;
    float *s, *bc;
    cudaGetSymbolAddress((void**)&xh,  g_xh);
    cudaGetSymbolAddress((void**)&wh,  g_wh);
    cudaGetSymbolAddress((void**)&bc,  g_bc);
    cudaGetSymbolAddress((void**)&qkv, g_qkv);
    cudaGetSymbolAddress((void**)&vT,  g_vT);
    cudaGetSymbolAddress((void**)&s,   g_s);
    cudaGetSymbolAddress((void**)&p,   g_p);

    cudaFuncSetAttribute(gemm_h<0>, cudaFuncAttributeMaxDynamicSharedMemorySize, SMEM_DYN);
    cudaFuncSetAttribute(gemm_h<2>, cudaFuncAttributeMaxDynamicSharedMemorySize, SMEM_DYN);

    // 0) fp16 conversions + bias concat
    conv_h<<<(MTOT * DIM / 4 + 255) / 256, 256>>>(x, xh, (long)MTOT * DIM / 4);
    conv_h<<<(DIM * DIM / 4 + 255) / 256, 256>>>(Wq, wh,               (long)DIM * DIM / 4);
    conv_h<<<(DIM * DIM / 4 + 255) / 256, 256>>>(Wk, wh + (long)DIM * DIM,     (long)DIM * DIM / 4);
    conv_h<<<(DIM * DIM / 4 + 255) / 256, 256>>>(Wv, wh + 2L * DIM * DIM, (long)DIM * DIM / 4);
    concat_bias<<<(DIM + 255) / 256, 256>>>(bq, bk, bv, bc);

    // 1) fused QKV: qkv[8192][3072] = xh @ wh^T + bc  (K=1024)
    dim3 gQKV(NQKV / 128, MTOT / 128, 1);
    gemm_h<0><<<gQKV, 256, SMEM_DYN>>>(xh, wh, bc, qkv,
                                       DIM, DIM, NQKV, DIM, 1.f, 0, 0, 0, 0);

    // 1b) transpose v slice -> vT
    dim3 gT(DIM / 32, MTOT / 32);
    transpose_v<<<gT, 256>>>(qkv, vT);

    // 2) S = (q @ k^T) * DIM^-0.5, batched over z
    dim3 gS(SEQ / 128, SEQ / 128, BATCH);
    gemm_h<2><<<gS, 256, SMEM_DYN>>>(qkv, qkv + DIM, nullptr, s,
                                     NQKV, NQKV, SEQ, DIM, 0.03125f,
                                     SEQ, SEQ, 0, (long)SEQ * SEQ);

    // 3) softmax rows -> fp16 P
    softmax_kernel<<<MTOT, 256>>>(s, p);

    // 4) out = P @ vT^T, batched over z
    dim3 gO(DIM / 128, SEQ / 128, BATCH);
    gemm_h<2><<<gO, 256, SMEM_DYN>>>(p, vT, nullptr, out,
                                     SEQ, MTOT, DIM, SEQ, 1.f,
                                     SEQ, 0, SEQ, (long)SEQ * DIM);
}